// round 3
// baseline (speedup 1.0000x reference)
#include <cuda_runtime.h>
#include <math.h>
#include <stdint.h>

#define NNODE  100000
#define EMAX   3200000
#define HDIM   128
#define CDIM   10
#define NGRAPH 512

// ---------------- scratch (device globals; no allocation allowed) -------
__device__ float g_hs  [NNODE * HDIM];   // GEMM output, pre-scaled by dinv[row]
__device__ float g_feat[NNODE * HDIM];   // aggregated features (layer output)
__device__ float g_h10 [NNODE * CDIM];   // last-layer GEMM output (scaled)
__device__ float g_o10 [NNODE * CDIM];   // last-layer aggregated output
__device__ int   g_deg [NNODE];
__device__ float g_dinv[NNODE];
__device__ int   g_rowptr[NNODE + 1];
__device__ int   g_cursor[NNODE];
__device__ int   g_col [EMAX];
__device__ int   g_bsum[128];
__device__ int   g_boff[128];
__device__ float g_sums[NGRAPH * CDIM];
__device__ float g_cnts[NGRAPH];

__device__ __forceinline__ int clampi(int v, int n) {
    return (v < 0) ? 0 : ((v >= n) ? n - 1 : v);
}

// ---------------- CSR build --------------------------------------------
__global__ void k_zero(int n) {
    int i = blockIdx.x * blockDim.x + threadIdx.x;
    if (i < n) g_deg[i] = 0;
    if (i < NGRAPH * CDIM) g_sums[i] = 0.0f;
    if (i < NGRAPH) g_cnts[i] = 0.0f;
}

__global__ void k_count(const int* __restrict__ ei, int E, int n) {
    int e = blockIdx.x * blockDim.x + threadIdx.x;
    if (e < E) atomicAdd(&g_deg[clampi(ei[E + e], n)], 1);
}

__global__ void k_dinv(int n) {
    int i = blockIdx.x * blockDim.x + threadIdx.x;
    if (i < n) g_dinv[i] = rsqrtf((float)(g_deg[i] + 1));   // +1 self loop
}

__global__ void k_scan1(int n) {          // per-1024-chunk sum
    __shared__ int s[1024];
    int t = threadIdx.x;
    int i = blockIdx.x * 1024 + t;
    s[t] = (i < n) ? g_deg[i] : 0;
    __syncthreads();
    for (int st = 512; st > 0; st >>= 1) {
        if (t < st) s[t] += s[t + st];
        __syncthreads();
    }
    if (t == 0) g_bsum[blockIdx.x] = s[0];
}

__global__ void k_scan2(int nb) {         // exclusive scan of <=128 chunk sums
    __shared__ int s[128];
    int t = threadIdx.x;
    int my = (t < nb) ? g_bsum[t] : 0;
    s[t] = my;
    __syncthreads();
    for (int st = 1; st < 128; st <<= 1) {
        int v = (t >= st) ? s[t - st] : 0;
        __syncthreads();
        s[t] += v;
        __syncthreads();
    }
    g_boff[t] = s[t] - my;                // exclusive
}

__global__ void k_scan3(int n, int E) {   // per-chunk exclusive scan + offset
    __shared__ int s[1024];
    int t = threadIdx.x;
    int i = blockIdx.x * 1024 + t;
    int v0 = (i < n) ? g_deg[i] : 0;
    s[t] = v0;
    __syncthreads();
    for (int st = 1; st < 1024; st <<= 1) {
        int v = (t >= st) ? s[t - st] : 0;
        __syncthreads();
        s[t] += v;
        __syncthreads();
    }
    if (i < n) {
        int excl = g_boff[blockIdx.x] + s[t] - v0;
        g_rowptr[i] = excl;
        g_cursor[i] = excl;
        if (i == n - 1) g_rowptr[n] = E;
    }
}

__global__ void k_fill(const int* __restrict__ ei, int E, int n) {
    int e = blockIdx.x * blockDim.x + threadIdx.x;
    if (e < E) {
        int src = clampi(ei[e], n);
        int dst = clampi(ei[E + e], n);
        int p = atomicAdd(&g_cursor[dst], 1);
        if (p >= 0 && p < E) g_col[p] = src;
    }
}

// ---------------- 128x128 GEMM: g_hs[r] = dinv[r] * (X[r] @ W) -----------
// K-chunked (32) so static smem stays under 48 KB.
__global__ void __launch_bounds__(256)
k_gemm128(const float* __restrict__ xin, const float* __restrict__ W,
          int n, int use_feat) {
    __shared__ float Ws[32 * 128];      // [k*128 + c]
    __shared__ float Xs[32 * 132];      // transposed: [k*132 + r]
    int tid = threadIdx.x;
    int rb = blockIdx.x * 128;
    const float* X = use_feat ? (const float*)g_feat : xin;

    int ty = tid >> 4, tx = tid & 15;
    int r0 = ty * 8, c0 = tx * 8;
    float acc[8][8];
    #pragma unroll
    for (int i = 0; i < 8; i++)
        #pragma unroll
        for (int j = 0; j < 8; j++) acc[i][j] = 0.f;

    for (int kc = 0; kc < 4; kc++) {
        // load W chunk: rows kc*32..+31, all 128 cols (1024 float4)
        #pragma unroll
        for (int i = tid; i < 1024; i += 256)
            ((float4*)Ws)[i] = ((const float4*)W)[kc * 1024 + i];
        // load X chunk transposed: 128 rows x 32 cols
        #pragma unroll
        for (int i = tid; i < 1024; i += 256) {
            int r = i & 127, k4 = i >> 7;           // k4 in 0..7
            float4 v = make_float4(0.f, 0.f, 0.f, 0.f);
            int gr = rb + r;
            if (gr < n) v = ((const float4*)X)[(long long)gr * 32 + kc * 8 + k4];
            int k = k4 * 4;
            Xs[(k + 0) * 132 + r] = v.x;
            Xs[(k + 1) * 132 + r] = v.y;
            Xs[(k + 2) * 132 + r] = v.z;
            Xs[(k + 3) * 132 + r] = v.w;
        }
        __syncthreads();

        #pragma unroll
        for (int k = 0; k < 32; k++) {
            float4 a0 = *(const float4*)&Xs[k * 132 + r0];
            float4 a1 = *(const float4*)&Xs[k * 132 + r0 + 4];
            float4 b0 = *(const float4*)&Ws[k * 128 + c0];
            float4 b1 = *(const float4*)&Ws[k * 128 + c0 + 4];
            float a[8] = {a0.x, a0.y, a0.z, a0.w, a1.x, a1.y, a1.z, a1.w};
            float b[8] = {b0.x, b0.y, b0.z, b0.w, b1.x, b1.y, b1.z, b1.w};
            #pragma unroll
            for (int i = 0; i < 8; i++)
                #pragma unroll
                for (int j = 0; j < 8; j++)
                    acc[i][j] = fmaf(a[i], b[j], acc[i][j]);
        }
        __syncthreads();
    }

    #pragma unroll
    for (int i = 0; i < 8; i++) {
        int gr = rb + r0 + i;
        if (gr < n) {
            float di = g_dinv[gr];
            float4 o0 = make_float4(acc[i][0] * di, acc[i][1] * di,
                                    acc[i][2] * di, acc[i][3] * di);
            float4 o1 = make_float4(acc[i][4] * di, acc[i][5] * di,
                                    acc[i][6] * di, acc[i][7] * di);
            ((float4*)g_hs)[(long long)gr * 32 + (c0 >> 2)]     = o0;
            ((float4*)g_hs)[(long long)gr * 32 + (c0 >> 2) + 1] = o1;
        }
    }
}

// ---------------- 128-wide pull aggregation -----------------------------
// g_feat[d] = relu( dinv[d]*(g_hs[d] + sum_in g_hs[s]) + bias )
__global__ void __launch_bounds__(256)
k_agg128(const float* __restrict__ bias, int n, int relu) {
    int w = (blockIdx.x * 256 + threadIdx.x) >> 5;
    int lane = threadIdx.x & 31;
    if (w >= n) return;
    const float4* base = (const float4*)g_hs;
    float4 acc = base[(long long)w * 32 + lane];   // self loop term
    int e0 = g_rowptr[w], e1 = g_rowptr[w + 1];
    for (int e = e0; e < e1; e += 32) {
        int me = e + lane;
        int ms = (me < e1) ? g_col[me] : 0;
        int cnt = min(32, e1 - e);
        #pragma unroll 4
        for (int j = 0; j < cnt; j++) {
            int s = __shfl_sync(0xffffffffu, ms, j);
            float4 v = base[(long long)s * 32 + lane];
            acc.x += v.x; acc.y += v.y; acc.z += v.z; acc.w += v.w;
        }
    }
    float di = g_dinv[w];
    float4 bv = ((const float4*)bias)[lane];
    float4 o;
    o.x = fmaf(di, acc.x, bv.x);
    o.y = fmaf(di, acc.y, bv.y);
    o.z = fmaf(di, acc.z, bv.z);
    o.w = fmaf(di, acc.w, bv.w);
    if (relu) {
        o.x = fmaxf(o.x, 0.f); o.y = fmaxf(o.y, 0.f);
        o.z = fmaxf(o.z, 0.f); o.w = fmaxf(o.w, 0.f);
    }
    ((float4*)g_feat)[(long long)w * 32 + lane] = o;
}

// ---------------- last layer: g_feat@W_out (128->10), scaled by dinv ----
__global__ void k_gemm10(const float* __restrict__ W, int n) {
    int idx = blockIdx.x * blockDim.x + threadIdx.x;
    if (idx >= n * CDIM) return;
    int r = idx / CDIM;
    int c = idx - r * CDIM;
    const float* xr = g_feat + (long long)r * HDIM;
    float s = 0.f;
    #pragma unroll 8
    for (int k = 0; k < HDIM; k++)
        s = fmaf(xr[k], __ldg(&W[k * CDIM + c]), s);
    g_h10[idx] = s * g_dinv[r];
}

// 10-wide aggregation (no relu)
__global__ void __launch_bounds__(256)
k_agg10(const float* __restrict__ bias, int n) {
    int w = (blockIdx.x * 256 + threadIdx.x) >> 5;
    int lane = threadIdx.x & 31;
    if (w >= n) return;
    float acc = (lane < CDIM) ? g_h10[(long long)w * CDIM + lane] : 0.f;
    int e0 = g_rowptr[w], e1 = g_rowptr[w + 1];
    for (int e = e0; e < e1; e += 32) {
        int me = e + lane;
        int ms = (me < e1) ? g_col[me] : 0;
        int cnt = min(32, e1 - e);
        for (int j = 0; j < cnt; j++) {
            int s = __shfl_sync(0xffffffffu, ms, j);
            if (lane < CDIM) acc += g_h10[(long long)s * CDIM + lane];
        }
    }
    if (lane < CDIM)
        g_o10[(long long)w * CDIM + lane] = fmaf(g_dinv[w], acc, bias[lane]);
}

// ---------------- global mean pool + log_softmax ------------------------
__global__ void k_pool(const int* __restrict__ batch, int n) {
    int i = blockIdx.x * blockDim.x + threadIdx.x;
    if (i >= n) return;
    int g = clampi(batch[i], NGRAPH);
    #pragma unroll
    for (int c = 0; c < CDIM; c++)
        atomicAdd(&g_sums[g * CDIM + c], g_o10[(long long)i * CDIM + c]);
    atomicAdd(&g_cnts[g], 1.0f);
}

__global__ void k_logsm(float* __restrict__ out) {
    int g = blockIdx.x * blockDim.x + threadIdx.x;
    if (g >= NGRAPH) return;
    float c = fmaxf(g_cnts[g], 1.0f);
    float p[CDIM];
    float m = -1e30f;
    #pragma unroll
    for (int i = 0; i < CDIM; i++) {
        p[i] = g_sums[g * CDIM + i] / c;
        m = fmaxf(m, p[i]);
    }
    float s = 0.f;
    #pragma unroll
    for (int i = 0; i < CDIM; i++) s += expf(p[i] - m);
    float l = logf(s);
    #pragma unroll
    for (int i = 0; i < CDIM; i++) out[g * CDIM + i] = p[i] - m - l;
}

// ---------------- launch -------------------------------------------------
extern "C" void kernel_launch(void* const* d_in, const int* in_sizes, int n_in,
                              void* d_out, int out_size) {
    const float* x     = (const float*)d_in[0];
    const int*   ei    = (const int*)d_in[1];     // int32 (JAX x64 disabled)
    const int*   batch = (const int*)d_in[2];     // int32
    const float* W_in  = (const float*)d_in[3];
    const float* b_in  = (const float*)d_in[4];
    const float* W_h0  = (const float*)d_in[5];
    const float* b_h0  = (const float*)d_in[6];
    const float* W_h1  = (const float*)d_in[7];
    const float* b_h1  = (const float*)d_in[8];
    const float* W_out = (const float*)d_in[9];
    const float* b_out = (const float*)d_in[10];

    int n = in_sizes[0] / HDIM;
    int E = in_sizes[1] / 2;

    const int TPB = 256;
    int nblk_n = (n + TPB - 1) / TPB;
    int nblk_e = (E + TPB - 1) / TPB;
    int nb = (n + 1023) / 1024;
    int gb = (n + 127) / 128;
    int agg_blocks = (n * 32 + TPB - 1) / TPB;

    // CSR build + degrees
    k_zero<<<nblk_n, TPB>>>(n);
    k_count<<<nblk_e, TPB>>>(ei, E, n);
    k_dinv<<<nblk_n, TPB>>>(n);
    k_scan1<<<nb, 1024>>>(n);
    k_scan2<<<1, 128>>>(nb);
    k_scan3<<<nb, 1024>>>(n, E);
    k_fill<<<nblk_e, TPB>>>(ei, E, n);

    // Layer 1
    k_gemm128<<<gb, 256>>>(x, W_in, n, 0);
    k_agg128<<<agg_blocks, TPB>>>(b_in, n, 1);
    // Layer 2
    k_gemm128<<<gb, 256>>>(x, W_h0, n, 1);
    k_agg128<<<agg_blocks, TPB>>>(b_h0, n, 1);
    // Layer 3
    k_gemm128<<<gb, 256>>>(x, W_h1, n, 1);
    k_agg128<<<agg_blocks, TPB>>>(b_h1, n, 1);
    // Layer 4 (128 -> 10), then aggregate 10-wide, no relu
    k_gemm10<<<(n * CDIM + TPB - 1) / TPB, TPB>>>(W_out, n);
    k_agg10<<<agg_blocks, TPB>>>(b_out, n);

    // Pool + log_softmax
    k_pool<<<nblk_n, TPB>>>(batch, n);
    k_logsm<<<(NGRAPH + TPB - 1) / TPB, TPB>>>((float*)d_out);
}

// round 4
// speedup vs baseline: 1.0819x; 1.0819x over previous
#include <cuda_runtime.h>
#include <cuda_fp16.h>
#include <math.h>
#include <stdint.h>

#define NNODE  100000
#define EMAX   3200000
#define HDIM   128
#define CDIM   10
#define NGRAPH 512

// ---------------- scratch (device globals; no allocation allowed) -------
__device__ __half g_hs16[NNODE * HDIM];  // GEMM output, dinv-scaled, fp16
__device__ float g_feat[NNODE * HDIM];   // aggregated features (layer output)
__device__ float g_h10 [NNODE * CDIM];   // last-layer GEMM output (scaled)
__device__ float g_o10 [NNODE * CDIM];   // last-layer aggregated output
__device__ int   g_deg [NNODE];
__device__ float g_dinv[NNODE];
__device__ int   g_rowptr[NNODE + 1];
__device__ int   g_cursor[NNODE];
__device__ int   g_col [EMAX];
__device__ int   g_bsum[128];
__device__ int   g_boff[128];
__device__ float g_sums[NGRAPH * CDIM];
__device__ float g_cnts[NGRAPH];

__device__ __forceinline__ int clampi(int v, int n) {
    return (v < 0) ? 0 : ((v >= n) ? n - 1 : v);
}

// packed f32x2 helpers (Blackwell FFMA2 — only reachable via PTX)
__device__ __forceinline__ unsigned long long dup2(float x) {
    unsigned long long d;
    unsigned int u = __float_as_uint(x);
    asm("mov.b64 %0, {%1, %1};" : "=l"(d) : "r"(u));
    return d;
}
__device__ __forceinline__ void ffma2(unsigned long long& d,
                                      unsigned long long a,
                                      unsigned long long b) {
    asm("fma.rn.f32x2 %0, %1, %2, %0;" : "+l"(d) : "l"(a), "l"(b));
}

// ---------------- CSR build --------------------------------------------
__global__ void k_zero(int n) {
    int i = blockIdx.x * blockDim.x + threadIdx.x;
    if (i < n) g_deg[i] = 0;
    if (i < NGRAPH * CDIM) g_sums[i] = 0.0f;
    if (i < NGRAPH) g_cnts[i] = 0.0f;
}

__global__ void k_count(const int* __restrict__ ei, int E, int n) {
    int e = blockIdx.x * blockDim.x + threadIdx.x;
    if (e < E) atomicAdd(&g_deg[clampi(ei[E + e], n)], 1);
}

__global__ void k_dinv(int n) {
    int i = blockIdx.x * blockDim.x + threadIdx.x;
    if (i < n) g_dinv[i] = rsqrtf((float)(g_deg[i] + 1));   // +1 self loop
}

__global__ void k_scan1(int n) {          // per-1024-chunk sum
    __shared__ int s[1024];
    int t = threadIdx.x;
    int i = blockIdx.x * 1024 + t;
    s[t] = (i < n) ? g_deg[i] : 0;
    __syncthreads();
    for (int st = 512; st > 0; st >>= 1) {
        if (t < st) s[t] += s[t + st];
        __syncthreads();
    }
    if (t == 0) g_bsum[blockIdx.x] = s[0];
}

__global__ void k_scan2(int nb) {         // exclusive scan of <=128 chunk sums
    __shared__ int s[128];
    int t = threadIdx.x;
    int my = (t < nb) ? g_bsum[t] : 0;
    s[t] = my;
    __syncthreads();
    for (int st = 1; st < 128; st <<= 1) {
        int v = (t >= st) ? s[t - st] : 0;
        __syncthreads();
        s[t] += v;
        __syncthreads();
    }
    g_boff[t] = s[t] - my;                // exclusive
}

__global__ void k_scan3(int n, int E) {   // per-chunk exclusive scan + offset
    __shared__ int s[1024];
    int t = threadIdx.x;
    int i = blockIdx.x * 1024 + t;
    int v0 = (i < n) ? g_deg[i] : 0;
    s[t] = v0;
    __syncthreads();
    for (int st = 1; st < 1024; st <<= 1) {
        int v = (t >= st) ? s[t - st] : 0;
        __syncthreads();
        s[t] += v;
        __syncthreads();
    }
    if (i < n) {
        int excl = g_boff[blockIdx.x] + s[t] - v0;
        g_rowptr[i] = excl;
        g_cursor[i] = excl;
        if (i == n - 1) g_rowptr[n] = E;
    }
}

__global__ void k_fill(const int* __restrict__ ei, int E, int n) {
    int e = blockIdx.x * blockDim.x + threadIdx.x;
    if (e < E) {
        int src = clampi(ei[e], n);
        int dst = clampi(ei[E + e], n);
        int p = atomicAdd(&g_cursor[dst], 1);
        if (p >= 0 && p < E) g_col[p] = src;
    }
}

// ---------------- 128x128 GEMM: g_hs16[r] = fp16(dinv[r] * (X[r] @ W)) --
// K-chunked (32). Packed f32x2 FMA: acc[i][jp] holds cols (c0+2jp, c0+2jp+1).
__global__ void __launch_bounds__(256)
k_gemm128(const float* __restrict__ xin, const float* __restrict__ W,
          int n, int use_feat) {
    __shared__ float Ws[32 * 128];      // [k*128 + c]
    __shared__ float Xs[32 * 132];      // transposed: [k*132 + r]
    int tid = threadIdx.x;
    int rb = blockIdx.x * 128;
    const float* X = use_feat ? (const float*)g_feat : xin;

    int ty = tid >> 4, tx = tid & 15;
    int r0 = ty * 8, c0 = tx * 8;
    unsigned long long acc[8][4];
    #pragma unroll
    for (int i = 0; i < 8; i++)
        #pragma unroll
        for (int j = 0; j < 4; j++) acc[i][j] = 0ull;

    for (int kc = 0; kc < 4; kc++) {
        #pragma unroll
        for (int i = tid; i < 1024; i += 256)
            ((float4*)Ws)[i] = ((const float4*)W)[kc * 1024 + i];
        #pragma unroll
        for (int i = tid; i < 1024; i += 256) {
            int r = i & 127, k4 = i >> 7;           // k4 in 0..7
            float4 v = make_float4(0.f, 0.f, 0.f, 0.f);
            int gr = rb + r;
            if (gr < n) v = ((const float4*)X)[(long long)gr * 32 + kc * 8 + k4];
            int k = k4 * 4;
            Xs[(k + 0) * 132 + r] = v.x;
            Xs[(k + 1) * 132 + r] = v.y;
            Xs[(k + 2) * 132 + r] = v.z;
            Xs[(k + 3) * 132 + r] = v.w;
        }
        __syncthreads();

        #pragma unroll
        for (int k = 0; k < 32; k++) {
            float4 a0 = *(const float4*)&Xs[k * 132 + r0];
            float4 a1 = *(const float4*)&Xs[k * 132 + r0 + 4];
            ulonglong2 bb0 = *(const ulonglong2*)&Ws[k * 128 + c0];
            ulonglong2 bb1 = *(const ulonglong2*)&Ws[k * 128 + c0 + 4];
            float a[8] = {a0.x, a0.y, a0.z, a0.w, a1.x, a1.y, a1.z, a1.w};
            #pragma unroll
            for (int i = 0; i < 8; i++) {
                unsigned long long ad = dup2(a[i]);
                ffma2(acc[i][0], ad, bb0.x);
                ffma2(acc[i][1], ad, bb0.y);
                ffma2(acc[i][2], ad, bb1.x);
                ffma2(acc[i][3], ad, bb1.y);
            }
        }
        __syncthreads();
    }

    #pragma unroll
    for (int i = 0; i < 8; i++) {
        int gr = rb + r0 + i;
        if (gr < n) {
            float di = g_dinv[gr];
            uint4 st;
            unsigned int* sp = (unsigned int*)&st;
            #pragma unroll
            for (int j = 0; j < 4; j++) {
                float2 f = *(float2*)&acc[i][j];
                __half2 h = __floats2half2_rn(f.x * di, f.y * di);
                sp[j] = *(unsigned int*)&h;
            }
            ((uint4*)g_hs16)[(long long)gr * 16 + (c0 >> 3)] = st;
        }
    }
}

// ---------------- 128-wide pull aggregation (fp16 gathers) --------------
// g_feat[d] = relu( dinv[d]*(hs16[d] + sum_in hs16[s]) + bias )
__global__ void __launch_bounds__(256)
k_agg128(const float* __restrict__ bias, int n, int relu) {
    int w = (blockIdx.x * 256 + threadIdx.x) >> 5;
    int lane = threadIdx.x & 31;
    if (w >= n) return;
    const uint2* base = (const uint2*)g_hs16;   // 32 x 8B per 256B row
    float4 acc;
    {
        uint2 v = base[(long long)w * 32 + lane];   // self loop
        float2 f0 = __half22float2(*(__half2*)&v.x);
        float2 f1 = __half22float2(*(__half2*)&v.y);
        acc.x = f0.x; acc.y = f0.y; acc.z = f1.x; acc.w = f1.y;
    }
    int e0 = g_rowptr[w], e1 = g_rowptr[w + 1];
    for (int e = e0; e < e1; e += 32) {
        int me = e + lane;
        int ms = (me < e1) ? g_col[me] : 0;
        int cnt = min(32, e1 - e);
        #pragma unroll 4
        for (int j = 0; j < cnt; j++) {
            int s = __shfl_sync(0xffffffffu, ms, j);
            uint2 v = base[(long long)s * 32 + lane];
            float2 f0 = __half22float2(*(__half2*)&v.x);
            float2 f1 = __half22float2(*(__half2*)&v.y);
            acc.x += f0.x; acc.y += f0.y; acc.z += f1.x; acc.w += f1.y;
        }
    }
    float di = g_dinv[w];
    float4 bv = ((const float4*)bias)[lane];
    float4 o;
    o.x = fmaf(di, acc.x, bv.x);
    o.y = fmaf(di, acc.y, bv.y);
    o.z = fmaf(di, acc.z, bv.z);
    o.w = fmaf(di, acc.w, bv.w);
    if (relu) {
        o.x = fmaxf(o.x, 0.f); o.y = fmaxf(o.y, 0.f);
        o.z = fmaxf(o.z, 0.f); o.w = fmaxf(o.w, 0.f);
    }
    ((float4*)g_feat)[(long long)w * 32 + lane] = o;
}

// ---------------- last layer: g_feat@W_out (128->10), scaled by dinv ----
__global__ void k_gemm10(const float* __restrict__ W, int n) {
    int idx = blockIdx.x * blockDim.x + threadIdx.x;
    if (idx >= n * CDIM) return;
    int r = idx / CDIM;
    int c = idx - r * CDIM;
    const float* xr = g_feat + (long long)r * HDIM;
    float s = 0.f;
    #pragma unroll 8
    for (int k = 0; k < HDIM; k++)
        s = fmaf(xr[k], __ldg(&W[k * CDIM + c]), s);
    g_h10[idx] = s * g_dinv[r];
}

// 10-wide aggregation (no relu)
__global__ void __launch_bounds__(256)
k_agg10(const float* __restrict__ bias, int n) {
    int w = (blockIdx.x * 256 + threadIdx.x) >> 5;
    int lane = threadIdx.x & 31;
    if (w >= n) return;
    float acc = (lane < CDIM) ? g_h10[(long long)w * CDIM + lane] : 0.f;
    int e0 = g_rowptr[w], e1 = g_rowptr[w + 1];
    for (int e = e0; e < e1; e += 32) {
        int me = e + lane;
        int ms = (me < e1) ? g_col[me] : 0;
        int cnt = min(32, e1 - e);
        for (int j = 0; j < cnt; j++) {
            int s = __shfl_sync(0xffffffffu, ms, j);
            if (lane < CDIM) acc += g_h10[(long long)s * CDIM + lane];
        }
    }
    if (lane < CDIM)
        g_o10[(long long)w * CDIM + lane] = fmaf(g_dinv[w], acc, bias[lane]);
}

// ---------------- global mean pool + log_softmax ------------------------
__global__ void k_pool(const int* __restrict__ batch, int n) {
    int i = blockIdx.x * blockDim.x + threadIdx.x;
    if (i >= n) return;
    int g = clampi(batch[i], NGRAPH);
    #pragma unroll
    for (int c = 0; c < CDIM; c++)
        atomicAdd(&g_sums[g * CDIM + c], g_o10[(long long)i * CDIM + c]);
    atomicAdd(&g_cnts[g], 1.0f);
}

__global__ void k_logsm(float* __restrict__ out) {
    int g = blockIdx.x * blockDim.x + threadIdx.x;
    if (g >= NGRAPH) return;
    float c = fmaxf(g_cnts[g], 1.0f);
    float p[CDIM];
    float m = -1e30f;
    #pragma unroll
    for (int i = 0; i < CDIM; i++) {
        p[i] = g_sums[g * CDIM + i] / c;
        m = fmaxf(m, p[i]);
    }
    float s = 0.f;
    #pragma unroll
    for (int i = 0; i < CDIM; i++) s += expf(p[i] - m);
    float l = logf(s);
    #pragma unroll
    for (int i = 0; i < CDIM; i++) out[g * CDIM + i] = p[i] - m - l;
}

// ---------------- launch -------------------------------------------------
extern "C" void kernel_launch(void* const* d_in, const int* in_sizes, int n_in,
                              void* d_out, int out_size) {
    const float* x     = (const float*)d_in[0];
    const int*   ei    = (const int*)d_in[1];
    const int*   batch = (const int*)d_in[2];
    const float* W_in  = (const float*)d_in[3];
    const float* b_in  = (const float*)d_in[4];
    const float* W_h0  = (const float*)d_in[5];
    const float* b_h0  = (const float*)d_in[6];
    const float* W_h1  = (const float*)d_in[7];
    const float* b_h1  = (const float*)d_in[8];
    const float* W_out = (const float*)d_in[9];
    const float* b_out = (const float*)d_in[10];

    int n = in_sizes[0] / HDIM;
    int E = in_sizes[1] / 2;

    const int TPB = 256;
    int nblk_n = (n + TPB - 1) / TPB;
    int nblk_e = (E + TPB - 1) / TPB;
    int nb = (n + 1023) / 1024;
    int gb = (n + 127) / 128;
    int agg_blocks = (n * 32 + TPB - 1) / TPB;

    // CSR build + degrees
    k_zero<<<nblk_n, TPB>>>(n);
    k_count<<<nblk_e, TPB>>>(ei, E, n);
    k_dinv<<<nblk_n, TPB>>>(n);
    k_scan1<<<nb, 1024>>>(n);
    k_scan2<<<1, 128>>>(nb);
    k_scan3<<<nb, 1024>>>(n, E);
    k_fill<<<nblk_e, TPB>>>(ei, E, n);

    // Layer 1
    k_gemm128<<<gb, 256>>>(x, W_in, n, 0);
    k_agg128<<<agg_blocks, TPB>>>(b_in, n, 1);
    // Layer 2
    k_gemm128<<<gb, 256>>>(x, W_h0, n, 1);
    k_agg128<<<agg_blocks, TPB>>>(b_h0, n, 1);
    // Layer 3
    k_gemm128<<<gb, 256>>>(x, W_h1, n, 1);
    k_agg128<<<agg_blocks, TPB>>>(b_h1, n, 1);
    // Layer 4 (128 -> 10), then aggregate 10-wide, no relu
    k_gemm10<<<(n * CDIM + TPB - 1) / TPB, TPB>>>(W_out, n);
    k_agg10<<<agg_blocks, TPB>>>(b_out, n);

    // Pool + log_softmax
    k_pool<<<nblk_n, TPB>>>(batch, n);
    k_logsm<<<(NGRAPH + TPB - 1) / TPB, TPB>>>((float*)d_out);
}

// round 5
// speedup vs baseline: 1.2312x; 1.1380x over previous
#include <cuda_runtime.h>
#include <cuda_fp16.h>
#include <math.h>
#include <stdint.h>

#define NNODE  100000
#define EMAX   3200000
#define HDIM   128
#define CDIM   10
#define NGRAPH 512

// ---------------- scratch (device globals; no allocation allowed) -------
__device__ __half g_hs16 [NNODE * HDIM]; // GEMM output, dinv-scaled, fp16
__device__ __half g_feat16[NNODE * HDIM];// aggregated features, fp16
__device__ float g_h10 [NNODE * CDIM];   // last-layer GEMM output (scaled)
__device__ int   g_deg [NNODE];
__device__ float g_dinv[NNODE];
__device__ int   g_rowptr[NNODE + 1];
__device__ int   g_cursor[NNODE];
__device__ int   g_col [EMAX];
__device__ int   g_bsum[128];
__device__ int   g_boff[128];
__device__ float g_sums[NGRAPH * CDIM];
__device__ float g_cnts[NGRAPH];

__device__ __forceinline__ int clampi(int v, int n) {
    return (v < 0) ? 0 : ((v >= n) ? n - 1 : v);
}

// packed f32x2 helpers (Blackwell FFMA2 — only reachable via PTX)
__device__ __forceinline__ unsigned long long dup2(float x) {
    unsigned long long d;
    unsigned int u = __float_as_uint(x);
    asm("mov.b64 %0, {%1, %1};" : "=l"(d) : "r"(u));
    return d;
}
__device__ __forceinline__ void ffma2(unsigned long long& d,
                                      unsigned long long a,
                                      unsigned long long b) {
    asm("fma.rn.f32x2 %0, %1, %2, %0;" : "+l"(d) : "l"(a), "l"(b));
}

// ---------------- CSR build --------------------------------------------
__global__ void k_zero(int n) {
    int i = blockIdx.x * blockDim.x + threadIdx.x;
    if (i < n) g_deg[i] = 0;
    if (i < NGRAPH * CDIM) g_sums[i] = 0.0f;
    if (i < NGRAPH) g_cnts[i] = 0.0f;
}

__global__ void k_count(const int* __restrict__ ei,
                        const int* __restrict__ batch, int E, int n) {
    int e = blockIdx.x * blockDim.x + threadIdx.x;
    if (e < E) atomicAdd(&g_deg[clampi(ei[E + e], n)], 1);
    if (e < n) atomicAdd(&g_cnts[clampi(batch[e], NGRAPH)], 1.0f);
}

__global__ void k_dinv(int n) {
    int i = blockIdx.x * blockDim.x + threadIdx.x;
    if (i < n) g_dinv[i] = rsqrtf((float)(g_deg[i] + 1));   // +1 self loop
}

__global__ void k_scan1(int n) {          // per-1024-chunk sum
    __shared__ int s[1024];
    int t = threadIdx.x;
    int i = blockIdx.x * 1024 + t;
    s[t] = (i < n) ? g_deg[i] : 0;
    __syncthreads();
    for (int st = 512; st > 0; st >>= 1) {
        if (t < st) s[t] += s[t + st];
        __syncthreads();
    }
    if (t == 0) g_bsum[blockIdx.x] = s[0];
}

__global__ void k_scan2(int nb) {         // exclusive scan of <=128 chunk sums
    __shared__ int s[128];
    int t = threadIdx.x;
    int my = (t < nb) ? g_bsum[t] : 0;
    s[t] = my;
    __syncthreads();
    for (int st = 1; st < 128; st <<= 1) {
        int v = (t >= st) ? s[t - st] : 0;
        __syncthreads();
        s[t] += v;
        __syncthreads();
    }
    g_boff[t] = s[t] - my;                // exclusive
}

__global__ void k_scan3(int n, int E) {   // per-chunk exclusive scan + offset
    __shared__ int s[1024];
    int t = threadIdx.x;
    int i = blockIdx.x * 1024 + t;
    int v0 = (i < n) ? g_deg[i] : 0;
    s[t] = v0;
    __syncthreads();
    for (int st = 1; st < 1024; st <<= 1) {
        int v = (t >= st) ? s[t - st] : 0;
        __syncthreads();
        s[t] += v;
        __syncthreads();
    }
    if (i < n) {
        int excl = g_boff[blockIdx.x] + s[t] - v0;
        g_rowptr[i] = excl;
        g_cursor[i] = excl;
        if (i == n - 1) g_rowptr[n] = E;
    }
}

__global__ void k_fill(const int* __restrict__ ei, int E, int n) {
    int e = blockIdx.x * blockDim.x + threadIdx.x;
    if (e < E) {
        int src = clampi(ei[e], n);
        int dst = clampi(ei[E + e], n);
        int p = atomicAdd(&g_cursor[dst], 1);
        if (p >= 0 && p < E) g_col[p] = src;
    }
}

// ---------------- 128x128 GEMM: g_hs16[r] = fp16(dinv[r] * (X[r] @ W)) --
// K-chunked (32). Packed f32x2 FMA. src==0: fp32 xin; src==1: g_feat16.
__global__ void __launch_bounds__(256)
k_gemm128(const float* __restrict__ xin, const float* __restrict__ W,
          int n, int src) {
    __shared__ float Ws[32 * 128];      // [k*128 + c]
    __shared__ float Xs[32 * 132];      // transposed: [k*132 + r]
    int tid = threadIdx.x;
    int rb = blockIdx.x * 128;

    int ty = tid >> 4, tx = tid & 15;
    int r0 = ty * 8, c0 = tx * 8;
    unsigned long long acc[8][4];
    #pragma unroll
    for (int i = 0; i < 8; i++)
        #pragma unroll
        for (int j = 0; j < 4; j++) acc[i][j] = 0ull;

    for (int kc = 0; kc < 4; kc++) {
        #pragma unroll
        for (int i = tid; i < 1024; i += 256)
            ((float4*)Ws)[i] = ((const float4*)W)[kc * 1024 + i];
        #pragma unroll
        for (int i = tid; i < 1024; i += 256) {
            int r = i & 127, k4 = i >> 7;           // k4 in 0..7
            float4 v = make_float4(0.f, 0.f, 0.f, 0.f);
            int gr = rb + r;
            if (gr < n) {
                if (src == 0) {
                    v = ((const float4*)xin)[(long long)gr * 32 + kc * 8 + k4];
                } else {
                    uint2 hv = ((const uint2*)g_feat16)[(long long)gr * 32 + kc * 8 + k4];
                    float2 f0 = __half22float2(*(__half2*)&hv.x);
                    float2 f1 = __half22float2(*(__half2*)&hv.y);
                    v = make_float4(f0.x, f0.y, f1.x, f1.y);
                }
            }
            int k = k4 * 4;
            Xs[(k + 0) * 132 + r] = v.x;
            Xs[(k + 1) * 132 + r] = v.y;
            Xs[(k + 2) * 132 + r] = v.z;
            Xs[(k + 3) * 132 + r] = v.w;
        }
        __syncthreads();

        #pragma unroll
        for (int k = 0; k < 32; k++) {
            float4 a0 = *(const float4*)&Xs[k * 132 + r0];
            float4 a1 = *(const float4*)&Xs[k * 132 + r0 + 4];
            ulonglong2 bb0 = *(const ulonglong2*)&Ws[k * 128 + c0];
            ulonglong2 bb1 = *(const ulonglong2*)&Ws[k * 128 + c0 + 4];
            float a[8] = {a0.x, a0.y, a0.z, a0.w, a1.x, a1.y, a1.z, a1.w};
            #pragma unroll
            for (int i = 0; i < 8; i++) {
                unsigned long long ad = dup2(a[i]);
                ffma2(acc[i][0], ad, bb0.x);
                ffma2(acc[i][1], ad, bb0.y);
                ffma2(acc[i][2], ad, bb1.x);
                ffma2(acc[i][3], ad, bb1.y);
            }
        }
        __syncthreads();
    }

    #pragma unroll
    for (int i = 0; i < 8; i++) {
        int gr = rb + r0 + i;
        if (gr < n) {
            float di = g_dinv[gr];
            uint4 st;
            unsigned int* sp = (unsigned int*)&st;
            #pragma unroll
            for (int j = 0; j < 4; j++) {
                float2 f = *(float2*)&acc[i][j];
                __half2 h = __floats2half2_rn(f.x * di, f.y * di);
                sp[j] = *(unsigned int*)&h;
            }
            ((uint4*)g_hs16)[(long long)gr * 16 + (c0 >> 3)] = st;
        }
    }
}

// ---------------- 128-wide pull aggregation (fp16 gathers) --------------
// o[d] = relu( dinv[d]*(hs16[d] + sum_in hs16[s]) + bias )
// fin==0: store o to g_feat16.   fin==1: also project o@W_out -> g_h10.
__global__ void __launch_bounds__(256)
k_agg128(const float* __restrict__ bias, const float* __restrict__ Wout,
         int n, int fin) {
    __shared__ float Wsm[HDIM * CDIM];
    if (fin) {
        for (int i = threadIdx.x; i < HDIM * CDIM; i += 256)
            Wsm[i] = Wout[i];
        __syncthreads();
    }
    int w = (blockIdx.x * 256 + threadIdx.x) >> 5;
    int lane = threadIdx.x & 31;
    if (w >= n) return;
    const uint2* base = (const uint2*)g_hs16;   // 32 x 8B per 256B row
    float4 acc;
    {
        uint2 v = base[(long long)w * 32 + lane];   // self loop
        float2 f0 = __half22float2(*(__half2*)&v.x);
        float2 f1 = __half22float2(*(__half2*)&v.y);
        acc.x = f0.x; acc.y = f0.y; acc.z = f1.x; acc.w = f1.y;
    }
    int e0 = g_rowptr[w], e1 = g_rowptr[w + 1];
    for (int e = e0; e < e1; e += 32) {
        int cnt = min(32, e1 - e);
        int me = e + lane;
        int ms = (me < e1) ? g_col[me] : 0;
        if (cnt == 32) {
            #pragma unroll
            for (int g = 0; g < 32; g += 8) {
                uint2 b[8];
                #pragma unroll
                for (int j = 0; j < 8; j++) {
                    int s = __shfl_sync(0xffffffffu, ms, g + j);
                    b[j] = base[(long long)s * 32 + lane];
                }
                #pragma unroll
                for (int j = 0; j < 8; j++) {
                    float2 f0 = __half22float2(*(__half2*)&b[j].x);
                    float2 f1 = __half22float2(*(__half2*)&b[j].y);
                    acc.x += f0.x; acc.y += f0.y; acc.z += f1.x; acc.w += f1.y;
                }
            }
        } else {
            for (int j = 0; j < cnt; j++) {
                int s = __shfl_sync(0xffffffffu, ms, j);
                uint2 v = base[(long long)s * 32 + lane];
                float2 f0 = __half22float2(*(__half2*)&v.x);
                float2 f1 = __half22float2(*(__half2*)&v.y);
                acc.x += f0.x; acc.y += f0.y; acc.z += f1.x; acc.w += f1.y;
            }
        }
    }
    float di = g_dinv[w];
    float4 bv = ((const float4*)bias)[lane];
    float4 o;
    o.x = fmaxf(fmaf(di, acc.x, bv.x), 0.f);
    o.y = fmaxf(fmaf(di, acc.y, bv.y), 0.f);
    o.z = fmaxf(fmaf(di, acc.z, bv.z), 0.f);
    o.w = fmaxf(fmaf(di, acc.w, bv.w), 0.f);

    if (!fin) {
        __half2 h0 = __floats2half2_rn(o.x, o.y);
        __half2 h1 = __floats2half2_rn(o.z, o.w);
        uint2 st;
        st.x = *(unsigned int*)&h0;
        st.y = *(unsigned int*)&h1;
        ((uint2*)g_feat16)[(long long)w * 32 + lane] = st;
    } else {
        // fused 128->10 projection: h10[w] = dinv[w] * (o_row @ W_out)
        float oa[4] = {o.x, o.y, o.z, o.w};
        float p[CDIM];
        #pragma unroll
        for (int c = 0; c < CDIM; c++) p[c] = 0.f;
        #pragma unroll
        for (int j = 0; j < 4; j++) {
            const float* wr = &Wsm[(4 * lane + j) * CDIM];
            #pragma unroll
            for (int c = 0; c < CDIM; c++)
                p[c] = fmaf(oa[j], wr[c], p[c]);
        }
        #pragma unroll
        for (int c = 0; c < CDIM; c++) {
            #pragma unroll
            for (int off = 16; off > 0; off >>= 1)
                p[c] += __shfl_xor_sync(0xffffffffu, p[c], off);
        }
        if (lane == 0) {
            float* dst = &g_h10[(long long)w * CDIM];
            #pragma unroll
            for (int c = 0; c < CDIM; c++) dst[c] = p[c] * di;
        }
    }
}

// 10-wide aggregation fused with mean-pool accumulation (no relu)
__global__ void __launch_bounds__(256)
k_agg10pool(const float* __restrict__ bias, const int* __restrict__ batch,
            int n) {
    int w = (blockIdx.x * 256 + threadIdx.x) >> 5;
    int lane = threadIdx.x & 31;
    if (w >= n) return;
    float acc = (lane < CDIM) ? g_h10[(long long)w * CDIM + lane] : 0.f;
    int e0 = g_rowptr[w], e1 = g_rowptr[w + 1];
    for (int e = e0; e < e1; e += 32) {
        int me = e + lane;
        int ms = (me < e1) ? g_col[me] : 0;
        int cnt = min(32, e1 - e);
        for (int j = 0; j < cnt; j++) {
            int s = __shfl_sync(0xffffffffu, ms, j);
            if (lane < CDIM) acc += g_h10[(long long)s * CDIM + lane];
        }
    }
    if (lane < CDIM) {
        float val = fmaf(g_dinv[w], acc, bias[lane]);
        int g = clampi(batch[w], NGRAPH);
        atomicAdd(&g_sums[g * CDIM + lane], val);
    }
}

__global__ void k_logsm(float* __restrict__ out) {
    int g = blockIdx.x * blockDim.x + threadIdx.x;
    if (g >= NGRAPH) return;
    float c = fmaxf(g_cnts[g], 1.0f);
    float p[CDIM];
    float m = -1e30f;
    #pragma unroll
    for (int i = 0; i < CDIM; i++) {
        p[i] = g_sums[g * CDIM + i] / c;
        m = fmaxf(m, p[i]);
    }
    float s = 0.f;
    #pragma unroll
    for (int i = 0; i < CDIM; i++) s += expf(p[i] - m);
    float l = logf(s);
    #pragma unroll
    for (int i = 0; i < CDIM; i++) out[g * CDIM + i] = p[i] - m - l;
}

// ---------------- launch -------------------------------------------------
extern "C" void kernel_launch(void* const* d_in, const int* in_sizes, int n_in,
                              void* d_out, int out_size) {
    const float* x     = (const float*)d_in[0];
    const int*   ei    = (const int*)d_in[1];
    const int*   batch = (const int*)d_in[2];
    const float* W_in  = (const float*)d_in[3];
    const float* b_in  = (const float*)d_in[4];
    const float* W_h0  = (const float*)d_in[5];
    const float* b_h0  = (const float*)d_in[6];
    const float* W_h1  = (const float*)d_in[7];
    const float* b_h1  = (const float*)d_in[8];
    const float* W_out = (const float*)d_in[9];
    const float* b_out = (const float*)d_in[10];

    int n = in_sizes[0] / HDIM;
    int E = in_sizes[1] / 2;

    const int TPB = 256;
    int nblk_n = (n + TPB - 1) / TPB;
    int nblk_e = (E + TPB - 1) / TPB;
    int nb = (n + 1023) / 1024;
    int gb = (n + 127) / 128;
    int agg_blocks = (n * 32 + TPB - 1) / TPB;

    // 1-3: degree/dinv (gemm L1 only needs these)
    k_zero<<<nblk_n, TPB>>>(n);
    k_count<<<nblk_e, TPB>>>(ei, batch, E, n);
    k_dinv<<<nblk_n, TPB>>>(n);
    // 4: layer-1 GEMM (positioned here so ncu -s captures it)
    k_gemm128<<<gb, 256>>>(x, W_in, n, 0);
    // 5-8: CSR build
    k_scan1<<<nb, 1024>>>(n);
    k_scan2<<<1, 128>>>(nb);
    k_scan3<<<nb, 1024>>>(n, E);
    k_fill<<<nblk_e, TPB>>>(ei, E, n);
    // 9: layer-1 aggregation
    k_agg128<<<agg_blocks, TPB>>>(b_in, W_out, n, 0);
    // Layer 2
    k_gemm128<<<gb, 256>>>(x, W_h0, n, 1);
    k_agg128<<<agg_blocks, TPB>>>(b_h0, W_out, n, 0);
    // Layer 3 (+fused 128->10 projection)
    k_gemm128<<<gb, 256>>>(x, W_h1, n, 1);
    k_agg128<<<agg_blocks, TPB>>>(b_h1, W_out, n, 1);
    // Layer 4 aggregation fused with pooling
    k_agg10pool<<<agg_blocks, TPB>>>(b_out, batch, n);
    // log_softmax
    k_logsm<<<(NGRAPH + TPB - 1) / TPB, TPB>>>((float*)d_out);
}

// round 7
// speedup vs baseline: 1.6555x; 1.3446x over previous
#include <cuda_runtime.h>
#include <cuda_fp16.h>
#include <math.h>
#include <stdint.h>

#define NNODE  100000
#define EMAX   3200000
#define HDIM   128
#define CDIM   10
#define NGRAPH 512

// ---------------- scratch (device globals; no allocation allowed) -------
__device__ __half g_hs16 [NNODE * HDIM]; // GEMM output, dinv-scaled, fp16
__device__ __half g_feat16[NNODE * HDIM];// aggregated features, fp16
__device__ uint2  g_bfrag[3 * 8 * 16 * 32]; // W in mma B-fragment layout
__device__ float g_h10 [NNODE * CDIM];   // last-layer projection (scaled)
__device__ int   g_deg [NNODE];
__device__ float g_dinv[NNODE];
__device__ int   g_rowptr[NNODE + 1];
__device__ int   g_cursor[NNODE];
__device__ int   g_col [EMAX];
__device__ int   g_bsum[128];
__device__ int   g_boff[128];
__device__ float g_sums[NGRAPH * CDIM];
__device__ float g_cnts[NGRAPH];

__device__ __forceinline__ int clampi(int v, int n) {
    return (v < 0) ? 0 : ((v >= n) ? n - 1 : v);
}

__device__ __forceinline__ uint32_t smem_u32(const void* p) {
    uint32_t a;
    asm("{ .reg .u64 t; cvta.to.shared.u64 t, %1; cvt.u32.u64 %0, t; }"
        : "=r"(a) : "l"(p));
    return a;
}

// ---------------- CSR build --------------------------------------------
__global__ void k_zero(int n) {
    int i = blockIdx.x * blockDim.x + threadIdx.x;
    if (i < n) g_deg[i] = 0;
    if (i < NGRAPH * CDIM) g_sums[i] = 0.0f;
    if (i < NGRAPH) g_cnts[i] = 0.0f;
}

__global__ void k_count(const int* __restrict__ ei,
                        const int* __restrict__ batch, int E, int n) {
    int e = blockIdx.x * blockDim.x + threadIdx.x;
    if (e < E) atomicAdd(&g_deg[clampi(ei[E + e], n)], 1);
    if (e < n) atomicAdd(&g_cnts[clampi(batch[e], NGRAPH)], 1.0f);
}

__global__ void k_dinv(int n) {
    int i = blockIdx.x * blockDim.x + threadIdx.x;
    if (i < n) g_dinv[i] = rsqrtf((float)(g_deg[i] + 1));
}

// Pack W (K x N, row-major) into mma.m16n8k16 B-fragment layout, fp16.
// For (layer l, kstep s, nfrag f, lane t):
//   kk = 2*(t%4), nn = t/4, kb = 16*s, nb = 8*f
//   x = half2(W[kb+kk][nb+nn],   W[kb+kk+1][nb+nn])
//   y = half2(W[kb+kk+8][nb+nn], W[kb+kk+9][nb+nn])
__global__ void k_prepW(const float* __restrict__ W0,
                        const float* __restrict__ W1,
                        const float* __restrict__ W2) {
    int idx = blockIdx.x * blockDim.x + threadIdx.x;
    if (idx >= 3 * 8 * 16 * 32) return;
    int lane = idx & 31;
    int f = (idx >> 5) & 15;
    int s = (idx >> 9) & 7;
    int l = idx >> 12;
    const float* W = (l == 0) ? W0 : (l == 1) ? W1 : W2;
    int kb = s * 16 + 2 * (lane & 3);
    int nn = f * 8 + (lane >> 2);
    __half2 h0 = __floats2half2_rn(W[kb * HDIM + nn], W[(kb + 1) * HDIM + nn]);
    __half2 h1 = __floats2half2_rn(W[(kb + 8) * HDIM + nn], W[(kb + 9) * HDIM + nn]);
    uint2 v;
    v.x = *(unsigned int*)&h0;
    v.y = *(unsigned int*)&h1;
    g_bfrag[idx] = v;
}

__global__ void k_scan1(int n) {
    __shared__ int s[1024];
    int t = threadIdx.x;
    int i = blockIdx.x * 1024 + t;
    s[t] = (i < n) ? g_deg[i] : 0;
    __syncthreads();
    for (int st = 512; st > 0; st >>= 1) {
        if (t < st) s[t] += s[t + st];
        __syncthreads();
    }
    if (t == 0) g_bsum[blockIdx.x] = s[0];
}

__global__ void k_scan2(int nb) {
    __shared__ int s[128];
    int t = threadIdx.x;
    int my = (t < nb) ? g_bsum[t] : 0;
    s[t] = my;
    __syncthreads();
    for (int st = 1; st < 128; st <<= 1) {
        int v = (t >= st) ? s[t - st] : 0;
        __syncthreads();
        s[t] += v;
        __syncthreads();
    }
    g_boff[t] = s[t] - my;
}

__global__ void k_scan3(int n, int E) {
    __shared__ int s[1024];
    int t = threadIdx.x;
    int i = blockIdx.x * 1024 + t;
    int v0 = (i < n) ? g_deg[i] : 0;
    s[t] = v0;
    __syncthreads();
    for (int st = 1; st < 1024; st <<= 1) {
        int v = (t >= st) ? s[t - st] : 0;
        __syncthreads();
        s[t] += v;
        __syncthreads();
    }
    if (i < n) {
        int excl = g_boff[blockIdx.x] + s[t] - v0;
        g_rowptr[i] = excl;
        g_cursor[i] = excl;
        if (i == n - 1) g_rowptr[n] = E;
    }
}

__global__ void k_fill(const int* __restrict__ ei, int E, int n) {
    int e = blockIdx.x * blockDim.x + threadIdx.x;
    if (e < E) {
        int src = clampi(ei[e], n);
        int dst = clampi(ei[E + e], n);
        int p = atomicAdd(&g_cursor[dst], 1);
        if (p >= 0 && p < E) g_col[p] = src;
    }
}

// ---------------- HMMA GEMM: g_hs16[r] = fp16(dinv[r] * (X[r] @ W)) -----
// 256 thr / 8 warps; warp w -> rows [rb+16w, rb+16w+16); full N=128, K=128.
#define APAD 136   // halves per smem row (272 B: conflict-free ldmatrix)
__global__ void __launch_bounds__(256)
k_gemm_mma(const float* __restrict__ xin, int layer, int n, int src) {
    __shared__ __half As[128 * APAD];
    int tid = threadIdx.x;
    int wid = tid >> 5, lane = tid & 31;
    int rb = blockIdx.x * 128;

    // fill A tile: 128 rows x 128 halves (16 x 16B granules per row)
    for (int i = tid; i < 2048; i += 256) {
        int r = i >> 4, j = i & 15;
        int gr = rb + r;
        uint4 v = make_uint4(0u, 0u, 0u, 0u);
        if (gr < n) {
            if (src == 0) {
                const float4* p = (const float4*)(xin + (long long)gr * HDIM + j * 8);
                float4 f0 = p[0], f1 = p[1];
                __half2 h0 = __floats2half2_rn(f0.x, f0.y);
                __half2 h1 = __floats2half2_rn(f0.z, f0.w);
                __half2 h2 = __floats2half2_rn(f1.x, f1.y);
                __half2 h3 = __floats2half2_rn(f1.z, f1.w);
                v.x = *(unsigned int*)&h0; v.y = *(unsigned int*)&h1;
                v.z = *(unsigned int*)&h2; v.w = *(unsigned int*)&h3;
            } else {
                v = *(const uint4*)(g_feat16 + (long long)gr * HDIM + j * 8);
            }
        }
        *(uint4*)&As[r * APAD + j * 8] = v;
    }
    __syncthreads();

    float acc[16][4];
    #pragma unroll
    for (int f = 0; f < 16; f++)
        #pragma unroll
        for (int j = 0; j < 4; j++) acc[f][j] = 0.f;

    const uint2* bf = g_bfrag + (layer * 8) * 16 * 32;
    int wr = wid * 16;                      // warp row offset in tile
    int g = lane >> 3, rr = lane & 7;
    // ldmatrix address pattern for A m16k16 (x4)
    uint32_t a_base = smem_u32(As) +
        (uint32_t)(((wr + (g & 1) * 8 + rr) * APAD) * 2);

    #pragma unroll
    for (int s = 0; s < 8; s++) {
        uint32_t a0, a1, a2, a3;
        uint32_t addr = a_base + (uint32_t)((s * 16 + (g >> 1) * 8) * 2);
        asm volatile("ldmatrix.sync.aligned.m8n8.x4.shared.b16 {%0,%1,%2,%3}, [%4];"
                     : "=r"(a0), "=r"(a1), "=r"(a2), "=r"(a3) : "r"(addr));
        const uint2* bs = bf + s * 16 * 32 + lane;
        #pragma unroll
        for (int f = 0; f < 16; f++) {
            uint2 b = __ldg(&bs[f * 32]);
            asm volatile(
                "mma.sync.aligned.m16n8k16.row.col.f32.f16.f16.f32 "
                "{%0,%1,%2,%3}, {%4,%5,%6,%7}, {%8,%9}, {%0,%1,%2,%3};"
                : "+f"(acc[f][0]), "+f"(acc[f][1]), "+f"(acc[f][2]), "+f"(acc[f][3])
                : "r"(a0), "r"(a1), "r"(a2), "r"(a3), "r"(b.x), "r"(b.y));
        }
    }

    // epilogue: d-frag rows = lane/4 and lane/4+8; cols = f*8 + 2*(lane%4)
    int r0 = rb + wr + (lane >> 2);
    int r1 = r0 + 8;
    float di0 = (r0 < n) ? g_dinv[r0] : 0.f;
    float di1 = (r1 < n) ? g_dinv[r1] : 0.f;
    #pragma unroll
    for (int f = 0; f < 16; f++) {
        int c = f * 8 + 2 * (lane & 3);
        if (r0 < n) {
            __half2 h = __floats2half2_rn(acc[f][0] * di0, acc[f][1] * di0);
            *(unsigned int*)(g_hs16 + (long long)r0 * HDIM + c) = *(unsigned int*)&h;
        }
        if (r1 < n) {
            __half2 h = __floats2half2_rn(acc[f][2] * di1, acc[f][3] * di1);
            *(unsigned int*)(g_hs16 + (long long)r1 * HDIM + c) = *(unsigned int*)&h;
        }
    }
}

// ---------------- 128-wide pull aggregation (fp16 gathers) --------------
__global__ void __launch_bounds__(256)
k_agg128(const float* __restrict__ bias, const float* __restrict__ Wout,
         int n, int fin) {
    __shared__ float Wsm[HDIM * CDIM];
    if (fin) {
        for (int i = threadIdx.x; i < HDIM * CDIM; i += 256)
            Wsm[i] = Wout[i];
        __syncthreads();
    }
    int w = (blockIdx.x * 256 + threadIdx.x) >> 5;
    int lane = threadIdx.x & 31;
    if (w >= n) return;
    const uint2* base = (const uint2*)g_hs16;
    float4 acc;
    {
        uint2 v = base[(long long)w * 32 + lane];
        float2 f0 = __half22float2(*(__half2*)&v.x);
        float2 f1 = __half22float2(*(__half2*)&v.y);
        acc.x = f0.x; acc.y = f0.y; acc.z = f1.x; acc.w = f1.y;
    }
    int e0 = g_rowptr[w], e1 = g_rowptr[w + 1];
    for (int e = e0; e < e1; e += 32) {
        int cnt = min(32, e1 - e);
        int me = e + lane;
        int ms = (me < e1) ? g_col[me] : 0;
        if (cnt == 32) {
            #pragma unroll
            for (int g = 0; g < 32; g += 8) {
                uint2 b[8];
                #pragma unroll
                for (int j = 0; j < 8; j++) {
                    int s = __shfl_sync(0xffffffffu, ms, g + j);
                    b[j] = base[(long long)s * 32 + lane];
                }
                #pragma unroll
                for (int j = 0; j < 8; j++) {
                    float2 f0 = __half22float2(*(__half2*)&b[j].x);
                    float2 f1 = __half22float2(*(__half2*)&b[j].y);
                    acc.x += f0.x; acc.y += f0.y; acc.z += f1.x; acc.w += f1.y;
                }
            }
        } else {
            for (int j = 0; j < cnt; j++) {
                int s = __shfl_sync(0xffffffffu, ms, j);
                uint2 v = base[(long long)s * 32 + lane];
                float2 f0 = __half22float2(*(__half2*)&v.x);
                float2 f1 = __half22float2(*(__half2*)&v.y);
                acc.x += f0.x; acc.y += f0.y; acc.z += f1.x; acc.w += f1.y;
            }
        }
    }
    float di = g_dinv[w];
    float4 bv = ((const float4*)bias)[lane];
    float4 o;
    o.x = fmaxf(fmaf(di, acc.x, bv.x), 0.f);
    o.y = fmaxf(fmaf(di, acc.y, bv.y), 0.f);
    o.z = fmaxf(fmaf(di, acc.z, bv.z), 0.f);
    o.w = fmaxf(fmaf(di, acc.w, bv.w), 0.f);

    if (!fin) {
        __half2 h0 = __floats2half2_rn(o.x, o.y);
        __half2 h1 = __floats2half2_rn(o.z, o.w);
        uint2 st;
        st.x = *(unsigned int*)&h0;
        st.y = *(unsigned int*)&h1;
        ((uint2*)g_feat16)[(long long)w * 32 + lane] = st;
    } else {
        float oa[4] = {o.x, o.y, o.z, o.w};
        float p[CDIM];
        #pragma unroll
        for (int c = 0; c < CDIM; c++) p[c] = 0.f;
        #pragma unroll
        for (int j = 0; j < 4; j++) {
            const float* wr = &Wsm[(4 * lane + j) * CDIM];
            #pragma unroll
            for (int c = 0; c < CDIM; c++)
                p[c] = fmaf(oa[j], wr[c], p[c]);
        }
        #pragma unroll
        for (int c = 0; c < CDIM; c++) {
            #pragma unroll
            for (int off = 16; off > 0; off >>= 1)
                p[c] += __shfl_xor_sync(0xffffffffu, p[c], off);
        }
        if (lane == 0) {
            float* dst = &g_h10[(long long)w * CDIM];
            #pragma unroll
            for (int c = 0; c < CDIM; c++) dst[c] = p[c] * di;
        }
    }
}

// 10-wide aggregation fused with mean-pool accumulation
__global__ void __launch_bounds__(256)
k_agg10pool(const float* __restrict__ bias, const int* __restrict__ batch,
            int n) {
    int w = (blockIdx.x * 256 + threadIdx.x) >> 5;
    int lane = threadIdx.x & 31;
    if (w >= n) return;
    float acc = (lane < CDIM) ? g_h10[(long long)w * CDIM + lane] : 0.f;
    int e0 = g_rowptr[w], e1 = g_rowptr[w + 1];
    for (int e = e0; e < e1; e += 32) {
        int me = e + lane;
        int ms = (me < e1) ? g_col[me] : 0;
        int cnt = min(32, e1 - e);
        for (int j = 0; j < cnt; j++) {
            int s = __shfl_sync(0xffffffffu, ms, j);
            if (lane < CDIM) acc += g_h10[(long long)s * CDIM + lane];
        }
    }
    if (lane < CDIM) {
        float val = fmaf(g_dinv[w], acc, bias[lane]);
        int g = clampi(batch[w], NGRAPH);
        atomicAdd(&g_sums[g * CDIM + lane], val);
    }
}

__global__ void k_logsm(float* __restrict__ out) {
    int g = blockIdx.x * blockDim.x + threadIdx.x;
    if (g >= NGRAPH) return;
    float c = fmaxf(g_cnts[g], 1.0f);
    float p[CDIM];
    float m = -1e30f;
    #pragma unroll
    for (int i = 0; i < CDIM; i++) {
        p[i] = g_sums[g * CDIM + i] / c;
        m = fmaxf(m, p[i]);
    }
    float s = 0.f;
    #pragma unroll
    for (int i = 0; i < CDIM; i++) s += expf(p[i] - m);
    float l = logf(s);
    #pragma unroll
    for (int i = 0; i < CDIM; i++) out[g * CDIM + i] = p[i] - m - l;
}

// ---------------- launch -------------------------------------------------
extern "C" void kernel_launch(void* const* d_in, const int* in_sizes, int n_in,
                              void* d_out, int out_size) {
    const float* x     = (const float*)d_in[0];
    const int*   ei    = (const int*)d_in[1];
    const int*   batch = (const int*)d_in[2];
    const float* W_in  = (const float*)d_in[3];
    const float* b_in  = (const float*)d_in[4];
    const float* W_h0  = (const float*)d_in[5];
    const float* b_h0  = (const float*)d_in[6];
    const float* W_h1  = (const float*)d_in[7];
    const float* b_h1  = (const float*)d_in[8];
    const float* W_out = (const float*)d_in[9];
    const float* b_out = (const float*)d_in[10];

    int n = in_sizes[0] / HDIM;
    int E = in_sizes[1] / 2;

    const int TPB = 256;
    int nblk_n = (n + TPB - 1) / TPB;
    int nblk_e = (E + TPB - 1) / TPB;
    int nb = (n + 1023) / 1024;
    int gb = (n + 127) / 128;
    int agg_blocks = (n * 32 + TPB - 1) / TPB;

    k_zero<<<nblk_n, TPB>>>(n);
    k_count<<<nblk_e, TPB>>>(ei, batch, E, n);
    k_dinv<<<nblk_n, TPB>>>(n);
    k_prepW<<<(3 * 8 * 16 * 32 + TPB - 1) / TPB, TPB>>>(W_in, W_h0, W_h1);
    // layer-1 GEMM early (profiling position)
    k_gemm_mma<<<gb, 256>>>(x, 0, n, 0);
    // CSR build
    k_scan1<<<nb, 1024>>>(n);
    k_scan2<<<1, 128>>>(nb);
    k_scan3<<<nb, 1024>>>(n, E);
    k_fill<<<nblk_e, TPB>>>(ei, E, n);
    // layer-1 aggregation
    k_agg128<<<agg_blocks, TPB>>>(b_in, W_out, n, 0);
    // Layer 2
    k_gemm_mma<<<gb, 256>>>(x, 1, n, 1);
    k_agg128<<<agg_blocks, TPB>>>(b_h0, W_out, n, 0);
    // Layer 3 (+fused 128->10 projection)
    k_gemm_mma<<<gb, 256>>>(x, 2, n, 1);
    k_agg128<<<agg_blocks, TPB>>>(b_h1, W_out, n, 1);
    // Layer 4 aggregation fused with pooling
    k_agg10pool<<<agg_blocks, TPB>>>(b_out, batch, n);
    k_logsm<<<(NGRAPH + TPB - 1) / TPB, TPB>>>((float*)d_out);
}